// round 4
// baseline (speedup 1.0000x reference)
#include <cuda_runtime.h>

#define B_  256
#define T_  4096
#define I_  63
#define H_  50
#define FC_ 64

#define APPROX_END 4032   // last 64 steps use exact tanhf (error washout)

// input-projection scratch, padded so the depth-4 prefetch ring never branches
__device__ float g_xz[(size_t)B_ * T_ * H_ + 512];

// ---------- packed f32x2 helpers (FFMA2 path, sm_103a) ----------
__device__ __forceinline__ unsigned long long pk2(float a, float b) {
    unsigned long long r;
    asm("mov.b64 %0,{%1,%2};" : "=l"(r) : "f"(a), "f"(b));
    return r;
}
__device__ __forceinline__ unsigned long long fma2(unsigned long long a,
                                                   unsigned long long b,
                                                   unsigned long long c) {
    unsigned long long d;
    asm("fma.rn.f32x2 %0,%1,%2,%3;" : "=l"(d) : "l"(a), "l"(b), "l"(c));
    return d;
}
__device__ __forceinline__ unsigned long long add2(unsigned long long a,
                                                   unsigned long long b) {
    unsigned long long d;
    asm("add.rn.f32x2 %0,%1,%2;" : "=l"(d) : "l"(a), "l"(b));
    return d;
}
__device__ __forceinline__ float2 up2(unsigned long long v) {
    float2 r;
    asm("mov.b64 {%0,%1},%2;" : "=f"(r.x), "=f"(r.y) : "l"(v));
    return r;
}
__device__ __forceinline__ float tanh_ap(float x) {
    float y;
    asm("tanh.approx.f32 %0,%1;" : "=f"(y) : "f"(x));
    return y;
}

// ================= Kernel A: xz[r,:] = x[r,:] @ W_ih^T + b_ih + b_hh ========
// Block = 128 threads / 256 rows (R=2 rows per thread to amortize W smem
// reloads). x staged in smem (coalesced in), results staged back (coalesced
// out). Stride-63 smem reads are bank-conflict-free (63 ≡ 31 mod 32).
__global__ void __launch_bounds__(128, 2) inproj_kernel(
    const float* __restrict__ x,
    const float* __restrict__ W_ih,
    const float* __restrict__ b_ih,
    const float* __restrict__ b_hh)
{
    __shared__ __align__(8) float Wsh[I_ * H_];      // Wsh[i*50+j] = W_ih[j][i]
    __shared__ __align__(8) float bsh[H_];
    __shared__ __align__(8) float xtile[256 * I_];   // 16128 floats, reused for out

    const int tid = threadIdx.x;
    const size_t row_base = (size_t)blockIdx.x * 256;

    for (int idx = tid; idx < I_ * H_; idx += 128) {
        int i = idx / H_, j = idx % H_;
        Wsh[idx] = W_ih[j * I_ + i];
    }
    for (int j = tid; j < H_; j += 128) bsh[j] = b_ih[j] + b_hh[j];

    // coalesced stage-in of 256 rows of x (16128 contiguous floats)
    const float* xblk = x + row_base * I_;
    for (int idx = tid; idx < 256 * I_; idx += 128) xtile[idx] = xblk[idx];
    __syncthreads();

    unsigned long long acc0[25], acc1[25];
    const float2* bp = (const float2*)bsh;
#pragma unroll
    for (int j2 = 0; j2 < 25; j2++) {
        float2 bv = bp[j2];
        acc0[j2] = pk2(bv.x, bv.y);
        acc1[j2] = acc0[j2];
    }

    const float* xr0 = xtile + tid * I_;
    const float* xr1 = xtile + (tid + 128) * I_;
#pragma unroll 9
    for (int i = 0; i < I_; i++) {
        float xv0 = xr0[i];
        float xv1 = xr1[i];
        unsigned long long x0d = pk2(xv0, xv0);
        unsigned long long x1d = pk2(xv1, xv1);
        const float2* wrow = (const float2*)(Wsh + i * H_);
#pragma unroll
        for (int j2 = 0; j2 < 25; j2++) {
            unsigned long long w = *(const unsigned long long*)(wrow + j2);
            acc0[j2] = fma2(w, x0d, acc0[j2]);
            acc1[j2] = fma2(w, x1d, acc1[j2]);
        }
    }
    __syncthreads();   // all x reads done; reuse xtile as output stage

    float2* o0 = (float2*)xtile + tid * 25;
    float2* o1 = (float2*)xtile + (tid + 128) * 25;
#pragma unroll
    for (int j2 = 0; j2 < 25; j2++) {
        o0[j2] = up2(acc0[j2]);
        o1[j2] = up2(acc1[j2]);
    }
    __syncthreads();

    // coalesced stage-out: 256*50 floats = 6400 float2, 50 per thread
    float2* oblk = (float2*)(g_xz + row_base * H_);
    const float2* xt2 = (const float2*)xtile;
#pragma unroll
    for (int u = 0; u < 50; u++) oblk[u * 128 + tid] = xt2[u * 128 + tid];
}

// ============ Kernel B: tanh recurrence, TWO warps per batch row + head =====
// Warp w, lane L (< 25) owns output j = w*25 + L (ONE output per lane).
// Per-warp per-step issue: 25 LDS.64 (h broadcast) + 25 FFMA2 + epilogue.
// h double-buffered in smem; one bar.sync per step orders STS before LDS.
__global__ void __launch_bounds__(64) rnn_kernel(
    const float* __restrict__ Whh,
    const float* __restrict__ W1, const float* __restrict__ b1,
    const float* __restrict__ W2, const float* __restrict__ b2,
    float* __restrict__ out)
{
    __shared__ __align__(8) float hbuf[2][52];
    __shared__ float c0s[FC_], c1s[FC_];

    const int tid  = threadIdx.x;
    const int warp = tid >> 5;
    const int lane = tid & 31;
    const int b    = blockIdx.x;
    const int Lc   = (lane < 25) ? lane : 24;     // clamp; dup writes benign
    const int j    = warp * 25 + Lc;              // owned output, 0..49

    // this lane's W_hh row, packed k-major (25 f32x2)
    unsigned long long wp[25];
    const float* wr = Whh + j * H_;
#pragma unroll
    for (int k2 = 0; k2 < 25; k2++)
        wp[k2] = pk2(__ldg(wr + 2 * k2), __ldg(wr + 2 * k2 + 1));

    hbuf[0][tid % 52] = 0.0f;   // covers 0..51 across 64 threads (dups ok)
    if (tid < 52) hbuf[0][tid] = 0.0f;
    __syncthreads();

    const float* xzp = g_xz + (size_t)b * T_ * H_ + j;

    // depth-4 prefetch ring, unconditional (g_xz padded)
    float xr[4];
#pragma unroll
    for (int u = 0; u < 4; u++) xr[u] = xzp[u * H_];

    const unsigned long long Z64 = pk2(0.0f, 0.0f);

#define RNN_STEP(UU, EXACTF) do {                                              \
    const int cb_ = (UU) & 1, nb_ = cb_ ^ 1;                                   \
    float xv = xr[UU];                                                         \
    xr[UU] = xzp[(size_t)(t + (UU) + 4) * H_];                                 \
    unsigned long long a0 = Z64, a1 = Z64, a2 = Z64, a3 = Z64;                 \
    _Pragma("unroll")                                                          \
    for (int k2 = 0; k2 < 25; k2++) {                                          \
        unsigned long long hk =                                                \
            *(const unsigned long long*)(&hbuf[cb_][2 * k2]);                  \
        switch (k2 & 3) {                                                      \
            case 0: a0 = fma2(hk, wp[k2], a0); break;                          \
            case 1: a1 = fma2(hk, wp[k2], a1); break;                          \
            case 2: a2 = fma2(hk, wp[k2], a2); break;                          \
            default: a3 = fma2(hk, wp[k2], a3); break;                         \
        }                                                                      \
    }                                                                          \
    float2 s = up2(add2(add2(a0, a1), add2(a2, a3)));                          \
    float av = (s.x + s.y) + xv;                                               \
    float hv;                                                                  \
    if (EXACTF) hv = tanhf(av); else hv = tanh_ap(av);                         \
    hbuf[nb_][j] = hv;                                                         \
    __syncthreads();                                                           \
} while (0)

    for (int t = 0; t < APPROX_END; t += 4) {
        RNN_STEP(0, false); RNN_STEP(1, false);
        RNN_STEP(2, false); RNN_STEP(3, false);
    }
    for (int t = APPROX_END; t < T_; t += 4) {
        RNN_STEP(0, true); RNN_STEP(1, true);
        RNN_STEP(2, true); RNN_STEP(3, true);
    }
#undef RNN_STEP

    // ---------- MLP head + argmax (final h in hbuf[0][0..49]) ----------
    // 64 threads, one FC unit each.
    const float* hf = hbuf[0];
    float fc = __ldg(b1 + tid);
#pragma unroll
    for (int k = 0; k < H_; k++) fc += hf[k] * __ldg(W1 + tid * H_ + k);
    fc = fmaxf(fc, 0.0f);
    c0s[tid] = fc * __ldg(W2 + tid);
    c1s[tid] = fc * __ldg(W2 + FC_ + tid);
    __syncthreads();
    if (tid == 0) {
        float p0 = __ldg(b2), p1 = __ldg(b2 + 1);
#pragma unroll
        for (int u = 0; u < FC_; u++) { p0 += c0s[u]; p1 += c1s[u]; }
        out[b] = (p1 > p0) ? 1.0f : 0.0f;   // argmax; softmax is monotone
    }
}

extern "C" void kernel_launch(void* const* d_in, const int* in_sizes, int n_in,
                              void* d_out, int out_size)
{
    const float* x    = (const float*)d_in[0];
    const float* W_ih = (const float*)d_in[1];
    const float* b_ih = (const float*)d_in[2];
    const float* W_hh = (const float*)d_in[3];
    const float* b_hh = (const float*)d_in[4];
    const float* W1   = (const float*)d_in[5];
    const float* b1   = (const float*)d_in[6];
    const float* W2   = (const float*)d_in[7];
    const float* b2   = (const float*)d_in[8];
    float* out = (float*)d_out;

    // Phase 1: input projection, 256 rows per 128-thread block (R=2)
    inproj_kernel<<<(B_ * T_) / 256, 128>>>(x, W_ih, b_ih, b_hh);

    // Phase 2: recurrence + head, two warps per batch row
    rnn_kernel<<<B_, 64>>>(W_hh, W1, b1, W2, b2, out);
}